// round 12
// baseline (speedup 1.0000x reference)
#include <cuda_runtime.h>
#include <cuda_bf16.h>
#include <math.h>
#include <stdint.h>

#define BATCH  64
#define HD     128
#define OUTC   10

#define PITCHV 136
#define V0_OFF 0
#define V1_OFF (16 * PITCHV * 2)            // 4352
#define XS_OFF (2 * 16 * PITCHV * 2)        // 8704
#define LG_OFF (XS_OFF + 16 * 256 * 4)      // 25088
#define RI_OFF (LG_OFF + 64)
#define LT_OFF (RI_OFF + 64)
#define MB_OFF (LT_OFF + 64)
#define SMEM_MAIN (MB_OFF + 16)

// Chain matrices permuted into mma.m16n8k16 B-fragment order (bf16, 16.7 MB).
// uint4 index: (c8*128 + kp*32 + lane), c8 = n>>3; per site: 4096 uint4.
//   packed pair = M[k0][n], M[k0+1][n]; k0 = kc*16 + 2*(lane&3) + reg*8
//   n = c8*8 + (lane>>2);  M[k][2h+d] = cores[m][k][d][h]
__device__ uint32_t g_perm[(size_t)255 * 16384];

// ---------------- helpers ----------------
__device__ __forceinline__ uint32_t smem_u32(const void* p) {
    uint32_t a;
    asm("{ .reg .u64 t; cvta.to.shared.u64 t, %1; cvt.u32.u64 %0, t; }" : "=r"(a) : "l"(p));
    return a;
}
__device__ __forceinline__ uint32_t cluster_rank() {
    uint32_t r; asm("mov.u32 %0, %%cluster_ctarank;" : "=r"(r)); return r;
}
__device__ __forceinline__ uint32_t mapa_peer(uint32_t addr, uint32_t rank) {
    uint32_t r;
    asm("mapa.shared::cluster.u32 %0, %1, %2;" : "=r"(r) : "r"(addr), "r"(rank));
    return r;
}
__device__ __forceinline__ void st_cluster_u16(uint32_t addr, unsigned short v) {
    asm volatile("st.shared::cluster.u16 [%0], %1;" :: "r"(addr), "h"(v) : "memory");
}
#define CLUSTER_ARRIVE() asm volatile("barrier.cluster.arrive.aligned;" ::: "memory")
#define CLUSTER_WAIT()   asm volatile("barrier.cluster.wait.aligned;"   ::: "memory")
#define MBARRIER_INIT(mbar, cnt) \
    asm volatile("mbarrier.init.shared.b64 [%0], %1;" :: "r"((uint32_t)(mbar)), "r"((uint32_t)(cnt)) : "memory")
#define MBAR_ARRIVE_REMOTE(addr) \
    asm volatile("mbarrier.arrive.shared::cluster.b64 _, [%0];" :: "r"((uint32_t)(addr)) : "memory")
#define FENCE_CLUSTER() asm volatile("fence.acq_rel.cluster;" ::: "memory")

#define MBAR_WAIT(mbar, par) do {                                            \
    uint32_t _done = 0;                                                      \
    while (!_done) {                                                         \
        asm volatile("{ .reg .pred p;"                                       \
            " mbarrier.try_wait.parity.acquire.cta.shared::cta.b64 p, [%1], %2, 0x989680;" \
            " selp.b32 %0, 1, 0, p; }"                                       \
            : "=r"(_done) : "r"((uint32_t)(mbar)), "r"((uint32_t)(par)) : "memory"); \
    } } while (0)

__device__ __forceinline__ void ldm_x4(uint32_t* r, uint32_t addr) {
    asm volatile("ldmatrix.sync.aligned.m8n8.x4.shared.b16 {%0,%1,%2,%3}, [%4];"
                 : "=r"(r[0]), "=r"(r[1]), "=r"(r[2]), "=r"(r[3]) : "r"(addr));
}
__device__ __forceinline__ void mma16816(float* c, const uint32_t* a,
                                         uint32_t b0, uint32_t b1) {
    asm volatile(
        "mma.sync.aligned.m16n8k16.row.col.f32.bf16.bf16.f32 "
        "{%0,%1,%2,%3}, {%4,%5,%6,%7}, {%8,%9}, {%0,%1,%2,%3};"
        : "+f"(c[0]), "+f"(c[1]), "+f"(c[2]), "+f"(c[3])
        : "r"(a[0]), "r"(a[1]), "r"(a[2]), "r"(a[3]), "r"(b0), "r"(b1));
}
__device__ __forceinline__ uint32_t packbf2(float a, float b) {
    __nv_bfloat162 t = __floats2bfloat162_rn(a, b);
    return *reinterpret_cast<uint32_t*>(&t);
}

// ---------------- pre-pass: cores fp32 -> fragment-permuted bf16 (as R9) -----
__global__ void __launch_bounds__(256) conv_perm(const float* __restrict__ cores)
{
    size_t gid = (size_t)blockIdx.x * 256 + threadIdx.x;   // 255*16384
    int u = (int)(gid & 16383);
    int m = (int)(gid >> 14);
    int j    = u & 3;
    int lane = (u >> 2) & 31;
    int kp   = (u >> 7) & 3;
    int c8   = (u >> 9) & 31;
    int kc = 2 * kp + (j >> 1);
    int k0 = kc * 16 + 2 * (lane & 3) + ((j & 1) << 3);
    int n  = c8 * 8 + (lane >> 2);
    int h = n >> 1, d = n & 1;
    const float* base = cores + (size_t)m * 32768;
    float lo = base[((size_t)k0 * 2 + d) * 128 + h];
    float hi = base[((size_t)(k0 + 1) * 2 + d) * 128 + h];
    g_perm[gid] = packbf2(lo, hi);
}

// ---------------- renorm (256 threads, full 16x128 buffer) ----------------
__device__ __forceinline__ void renorm(char* vb, float* LOGS, float* RINV,
                                       float* LTOT, bool final_)
{
    const int tid = threadIdx.x;
    int bb = tid >> 4, seg = tid & 15;
    __nv_bfloat16* vr = (__nv_bfloat16*)(vb + bb * (PITCHV * 2));
    float s = 0.f;
    #pragma unroll
    for (int j = 0; j < 8; ++j) {
        float f = __bfloat162float(vr[seg * 8 + j]);
        s = fmaf(f, f, s);
    }
    #pragma unroll
    for (int o = 8; o > 0; o >>= 1) s += __shfl_xor_sync(0xffffffffu, s, o);
    if (seg == 0) {
        float nrm = fmaxf(sqrtf(s), 1e-30f);
        if (final_) { RINV[bb] = 1.f / nrm; LTOT[bb] = LOGS[bb] + logf(nrm); }
        else        { LOGS[bb] += logf(nrm); RINV[bb] = 1.f / nrm; }
    }
    __syncthreads();
    if (!final_) {
        float ri = RINV[bb];
        #pragma unroll
        for (int j = 0; j < 8; ++j)
            vr[seg * 8 + j] = __float2bfloat16(__bfloat162float(vr[seg * 8 + j]) * ri);
        __syncthreads();
    }
}

// ---------------- one chain step (2-CTA n-split, mbarrier sync) -------------
__device__ __forceinline__ void step(
    int m, uint4* __restrict__ Bcur, uint4* __restrict__ Bnext, bool pre,
    char* sm, uint32_t smb, uint32_t peer_smb, uint32_t peer_mbar,
    uint32_t fragbase, int wcg, int l15, int lhi, int r, int q,
    float* XS, float* LOGS, float* RINV, float* LTOT)
{
    // wait phase m: peer's half of V(m) landed in local buffer (m&1 parity)
    MBAR_WAIT(smb + MB_OFF, m & 1);

    if (m > 0 && (m & 15) == 0)
        renorm(sm + ((m & 1) ? V1_OFF : V0_OFF), LOGS, RINV, LTOT, false);

    const uint32_t vro = smb + ((m & 1) ? V1_OFF : V0_OFF);
    const int      vwo = (m & 1) ? V0_OFF : V1_OFF;

    uint32_t A[8][4];
    #pragma unroll
    for (int kc = 0; kc < 8; ++kc)
        ldm_x4(A[kc], vro + (uint32_t)(l15 * PITCHV + kc * 16 + lhi) * 2);

    float acc[2][4];
    #pragma unroll
    for (int i = 0; i < 2; ++i)
        #pragma unroll
        for (int j = 0; j < 4; ++j) acc[i][j] = 0.f;

    #pragma unroll
    for (int kc = 0; kc < 8; ++kc)
        #pragma unroll
        for (int nt = 0; nt < 2; ++nt) {
            const uint4& v = Bcur[nt * 4 + (kc >> 1)];
            uint32_t b0 = (kc & 1) ? v.z : v.x;
            uint32_t b1 = (kc & 1) ? v.w : v.y;
            mma16816(acc[nt], A[kc], b0, b1);
        }

    // epilogue: 2 h-values x 2 rows per thread; write local + push to peer
    const float xa = XS[r * 256 + m + 1];
    const float xb = XS[(r + 8) * 256 + m + 1];
    #pragma unroll
    for (int nt = 0; nt < 2; ++nt) {
        int h = wcg * 8 + nt * 4 + q;
        float v0 = fmaf(xa, acc[nt][1], (1.f - xa) * acc[nt][0]);
        float v1 = fmaf(xb, acc[nt][3], (1.f - xb) * acc[nt][2]);
        unsigned short h0 = __bfloat16_as_ushort(__float2bfloat16(v0));
        unsigned short h1 = __bfloat16_as_ushort(__float2bfloat16(v1));
        uint32_t off0 = (uint32_t)(vwo + r * (PITCHV * 2) + h * 2);
        uint32_t off1 = (uint32_t)(vwo + (r + 8) * (PITCHV * 2) + h * 2);
        *(unsigned short*)(sm + off0) = h0;
        *(unsigned short*)(sm + off1) = h1;
        st_cluster_u16(peer_smb + off0, h0);
        st_cluster_u16(peer_smb + off1, h1);
    }

    __syncthreads();                 // all local threads' stores done
    if (threadIdx.x == 0) {
        FENCE_CLUSTER();             // order all threads' remote stores
        MBAR_ARRIVE_REMOTE(peer_mbar);   // completes peer's phase m+1
    }

    if (pre) {   // prefetch B(m+1) in the slack
        const uint4* bp = (const uint4*)g_perm + ((size_t)(m + 1) << 12) + fragbase;
        #pragma unroll
        for (int nt = 0; nt < 2; ++nt)
            #pragma unroll
            for (int kp = 0; kp < 4; ++kp)
                Bnext[nt * 4 + kp] = bp[nt * 128 + kp * 32];
    }
}

// ---------------- main: 2-CTA cluster, 8 warps/CTA, n-split, mbarrier -------
__global__ void __launch_bounds__(256, 1) __cluster_dims__(2, 1, 1) mps_chain(
    const float* __restrict__ x, const float* __restrict__ core0,
    const float* __restrict__ classifier, float* __restrict__ out)
{
    __shared__ char sm[SMEM_MAIN];
    uint32_t smb = smem_u32(sm);
    const int tid = threadIdx.x, lane = tid & 31, w = tid >> 5;
    const uint32_t rank = cluster_rank();
    const int b0 = (blockIdx.x >> 1) * 16;
    const int wcg = (int)rank * 8 + w;            // global 16-col slice 0..15
    const uint32_t peer_smb  = mapa_peer(smb, rank ^ 1);
    const uint32_t peer_mbar = peer_smb + MB_OFF;

    float* XS   = (float*)(sm + XS_OFF);
    float* LOGS = (float*)(sm + LG_OFF);
    float* RINV = (float*)(sm + RI_OFF);
    float* LTOT = (float*)(sm + LT_OFF);

    if (tid == 0) MBARRIER_INIT(smb + MB_OFF, 1);
    __syncthreads();
    CLUSTER_ARRIVE(); CLUSTER_WAIT();   // both mbarriers initialized

    const int l15 = lane & 15, lhi = (lane >> 4) << 3;
    const int r = lane >> 2, q = lane & 3;
    const uint32_t fragbase = (uint32_t)(2 * wcg) * 128 + lane;  // uint4 units

    // preload B(0)
    uint4 B0[8], B1[8];
    {
        const uint4* bp = (const uint4*)g_perm + fragbase;
        #pragma unroll
        for (int nt = 0; nt < 2; ++nt)
            #pragma unroll
            for (int kp = 0; kp < 4; ++kp)
                B0[nt * 4 + kp] = bp[nt * 128 + kp * 32];
    }

    #pragma unroll
    for (int it = 0; it < 16; ++it) {
        int idx = it * 256 + tid;
        XS[idx] = x[(size_t)(b0 + (idx >> 8)) * 256 + (idx & 255)];
    }
    if (tid < 16) LOGS[tid] = 0.f;
    __syncthreads();

    // init full V0 locally (replicated in both CTAs)
    #pragma unroll
    for (int it = 0; it < 8; ++it) {
        int idx = it * 256 + tid;
        int bb = idx >> 7, h = idx & 127;
        float xv = XS[bb * 256];
        float v = (1.f - xv) * core0[h] + xv * core0[HD + h];
        *(__nv_bfloat16*)(sm + V0_OFF + bb * (PITCHV * 2) + h * 2) = __float2bfloat16(v);
    }
    __syncthreads();                     // local V0 visible to all local threads
    if (tid == 0) {
        FENCE_CLUSTER();
        MBAR_ARRIVE_REMOTE(peer_mbar);   // arm phase 0 on the peer
    }

    for (int mm = 0; mm < 127; ++mm) {
        step(2 * mm,     B0, B1, true, sm, smb, peer_smb, peer_mbar,
             fragbase, wcg, l15, lhi, r, q, XS, LOGS, RINV, LTOT);
        step(2 * mm + 1, B1, B0, true, sm, smb, peer_smb, peer_mbar,
             fragbase, wcg, l15, lhi, r, q, XS, LOGS, RINV, LTOT);
    }
    step(254, B0, B1, false, sm, smb, peer_smb, peer_mbar,
         fragbase, wcg, l15, lhi, r, q, XS, LOGS, RINV, LTOT);

    MBAR_WAIT(smb + MB_OFF, 1);          // phase 255: full V(255) in V1

    renorm(sm + V1_OFF, LOGS, RINV, LTOT, true);
    __syncthreads();

    if (rank == 0 && tid < 16 * OUTC) {
        int bb = tid / OUTC, o = tid % OUTC;
        const __nv_bfloat16* vr = (const __nv_bfloat16*)(sm + V1_OFF + bb * (PITCHV * 2));
        float s = 0.f;
        #pragma unroll
        for (int h = 0; h < HD; ++h)
            s = fmaf(__bfloat162float(vr[h]), classifier[o * HD + h], s);
        out[(size_t)(b0 + bb) * OUTC + o] = s * RINV[bb] + LTOT[bb];
    }
}

extern "C" void kernel_launch(void* const* d_in, const int* in_sizes, int n_in,
                              void* d_out, int out_size)
{
    (void)in_sizes; (void)n_in; (void)out_size;
    const float* x          = (const float*)d_in[0];
    const float* core0      = (const float*)d_in[1];
    const float* cores      = (const float*)d_in[2];
    const float* classifier = (const float*)d_in[3];
    float*       out        = (float*)d_out;

    conv_perm<<<16320, 256>>>(cores);                    // 255*16384 threads
    mps_chain<<<8, 256>>>(x, core0, classifier, out);    // 4 clusters x 2 CTAs
}

// round 13
// speedup vs baseline: 1.5930x; 1.5930x over previous
#include <cuda_runtime.h>
#include <cuda_bf16.h>
#include <math.h>
#include <stdint.h>

#define BATCH  64
#define HD     128
#define OUTC   10

#define PITCHV 136      // V row pitch, bf16 elems
#define V0_OFF 0
#define V1_OFF (16 * PITCHV * 2)            // 4352
#define XS_OFF (2 * 16 * PITCHV * 2)        // 8704
#define LG_OFF (XS_OFF + 16 * 256 * 4)      // 25088
#define RI_OFF (LG_OFF + 64)
#define LT_OFF (RI_OFF + 64)
#define SMEM_MAIN (LT_OFF + 64)

// Chain matrices permuted into mma.m16n8k16 B-fragment order (bf16, 16.7 MB):
// uint4 index: m*4096 + wc*512 + nt*128 + kp*32 + lane
//   within uint4, u32 j: kc = 2*kp + (j>>1); reg = j&1
//   packed pair = M[k0][n], M[k0+1][n]; k0 = kc*16 + 2*(lane&3) + reg*8
//   n = (wc*4+nt)*8 + (lane>>2);  M[k][2h+d] = cores[m][k][d][h]
__device__ uint32_t g_perm[(size_t)255 * 16384];

// ---------------- helpers ----------------
__device__ __forceinline__ uint32_t smem_u32(const void* p) {
    uint32_t a;
    asm("{ .reg .u64 t; cvta.to.shared.u64 t, %1; cvt.u32.u64 %0, t; }" : "=r"(a) : "l"(p));
    return a;
}
__device__ __forceinline__ void ldm_x4(uint32_t* r, uint32_t addr) {
    asm volatile("ldmatrix.sync.aligned.m8n8.x4.shared.b16 {%0,%1,%2,%3}, [%4];"
                 : "=r"(r[0]), "=r"(r[1]), "=r"(r[2]), "=r"(r[3]) : "r"(addr));
}
__device__ __forceinline__ void mma16816(float* c, const uint32_t* a,
                                         uint32_t b0, uint32_t b1) {
    asm volatile(
        "mma.sync.aligned.m16n8k16.row.col.f32.bf16.bf16.f32 "
        "{%0,%1,%2,%3}, {%4,%5,%6,%7}, {%8,%9}, {%0,%1,%2,%3};"
        : "+f"(c[0]), "+f"(c[1]), "+f"(c[2]), "+f"(c[3])
        : "r"(a[0]), "r"(a[1]), "r"(a[2]), "r"(a[3]), "r"(b0), "r"(b1));
}
__device__ __forceinline__ uint32_t packbf2(float a, float b) {
    __nv_bfloat162 t = __floats2bfloat162_rn(a, b);
    return *reinterpret_cast<uint32_t*>(&t);
}

// ---------------- pre-pass: coalesced SMEM-staged fragment permute ----------
// One CTA per site m. For each k-chunk kp (32 k-rows = 32 KB fp32):
//   stage chunk in SMEM (coalesced float4 reads), gather fragments (LDS),
//   write g_perm coalesced.
__global__ void __launch_bounds__(256) conv_perm(const float* __restrict__ cores)
{
    __shared__ float ts[32][257];    // 32 k-rows x 256 cols (+1 pad), ~32.9 KB
    const int m = blockIdx.x, tid = threadIdx.x;
    const float* src = cores + (size_t)m * 32768;
    uint32_t* dst = g_perm + (size_t)m * 16384;

    for (int kp = 0; kp < 4; ++kp) {
        // load 32x256 fp32 chunk, coalesced float4
        #pragma unroll
        for (int it = 0; it < 8; ++it) {
            int idx = it * 256 + tid;              // 2048 float4
            int k = idx >> 6, cg = (idx & 63) * 4;
            float4 v = *(const float4*)(src + (size_t)(kp * 32 + k) * 256 + cg);
            ts[k][cg + 0] = v.x; ts[k][cg + 1] = v.y;
            ts[k][cg + 2] = v.z; ts[k][cg + 3] = v.w;
        }
        __syncthreads();

        // gather + coalesced write: 4096 u32 for this kp
        #pragma unroll
        for (int it = 0; it < 16; ++it) {
            int lin = it * 256 + tid;              // 0..4095
            int j    = lin & 3;
            int lane = (lin >> 2) & 31;
            int c8   = lin >> 7;                   // 0..31
            int k0l = 16 * (j >> 1) + 2 * (lane & 3) + ((j & 1) << 3);  // local k
            int n = c8 * 8 + (lane >> 2);
            int col = (n & 1) * 128 + (n >> 1);    // d*128 + h
            float lo = ts[k0l][col];
            float hi = ts[k0l + 1][col];
            dst[(size_t)c8 * 512 + kp * 128 + (lin & 127)] = packbf2(lo, hi);
        }
        __syncthreads();
    }
}

// ---------------- one chain step (R9 structure, interleaved ldm/mma) --------
__device__ __forceinline__ void chain_step(
    int m, bool prefetch, uint4* __restrict__ Bcur, uint4* __restrict__ Bnext,
    char* sm, uint32_t smb, uint32_t fragbase,
    int lane, int wc, int l15, int lhi, int r, int q)
{
    float* XS   = (float*)(sm + XS_OFF);
    float* LOGS = (float*)(sm + LG_OFF);
    float* RINV = (float*)(sm + RI_OFF);

    // prefetch B(m+1): 16 coalesced LDG.128, consumed next step
    if (prefetch) {
        const uint4* bp = (const uint4*)g_perm + ((size_t)(m + 1) << 12) + fragbase;
        #pragma unroll
        for (int i = 0; i < 16; ++i)
            Bnext[i] = bp[i * 32];
    }

    const uint32_t vr = smb + ((m & 1) ? V1_OFF : V0_OFF);
    char* vw = sm + ((m & 1) ? V0_OFF : V1_OFF);

    __syncthreads();   // V(m) writes visible

    float acc[4][4];
    #pragma unroll
    for (int i = 0; i < 4; ++i)
        #pragma unroll
        for (int j = 0; j < 4; ++j) acc[i][j] = 0.f;

    // interleaved A-ldmatrix / MMA: 2-deep LDSM pipeline
    uint32_t A[8][4];
    ldm_x4(A[0], vr + (uint32_t)(l15 * PITCHV + 0 * 16 + lhi) * 2);
    ldm_x4(A[1], vr + (uint32_t)(l15 * PITCHV + 1 * 16 + lhi) * 2);
    #pragma unroll
    for (int kc = 0; kc < 8; ++kc) {
        if (kc + 2 < 8)
            ldm_x4(A[kc + 2], vr + (uint32_t)(l15 * PITCHV + (kc + 2) * 16 + lhi) * 2);
        #pragma unroll
        for (int nt = 0; nt < 4; ++nt) {
            const uint4& v = Bcur[nt * 4 + (kc >> 1)];
            uint32_t b0 = (kc & 1) ? v.z : v.x;
            uint32_t b1 = (kc & 1) ? v.w : v.y;
            mma16816(acc[nt], A[kc], b0, b1);
        }
    }

    // epilogue -> write buffer (ping-pong, no extra barrier)
    const float xa = XS[r * 256 + m + 1];
    const float xb = XS[(r + 8) * 256 + m + 1];
    #pragma unroll
    for (int nt = 0; nt < 4; ++nt) {
        int h = wc * 16 + nt * 4 + q;
        float v0 = fmaf(xa, acc[nt][1], (1.f - xa) * acc[nt][0]);
        float v1 = fmaf(xb, acc[nt][3], (1.f - xb) * acc[nt][2]);
        *(__nv_bfloat16*)(vw + r * (PITCHV * 2) + h * 2) = __float2bfloat16(v0);
        *(__nv_bfloat16*)(vw + (r + 8) * (PITCHV * 2) + h * 2) = __float2bfloat16(v1);
    }

    // periodic renormalization on the write buffer
    if (((m + 1) & 15) == 0 && m < 254) {
        const int tid = threadIdx.x;
        __syncthreads();
        int bb = tid >> 4, seg = tid & 15;
        __nv_bfloat16* vrow = (__nv_bfloat16*)(vw + bb * (PITCHV * 2));
        float s = 0.f;
        #pragma unroll
        for (int j = 0; j < 8; ++j) {
            float f = __bfloat162float(vrow[seg * 8 + j]);
            s = fmaf(f, f, s);
        }
        #pragma unroll
        for (int o = 8; o > 0; o >>= 1) s += __shfl_xor_sync(0xffffffffu, s, o);
        if (seg == 0) {
            float nrm = fmaxf(sqrtf(s), 1e-30f);
            LOGS[bb] += logf(nrm);
            RINV[bb] = 1.f / nrm;
        }
        __syncthreads();
        float ri = RINV[bb];
        #pragma unroll
        for (int j = 0; j < 8; ++j)
            vrow[seg * 8 + j] = __float2bfloat16(__bfloat162float(vrow[seg * 8 + j]) * ri);
        // visibility covered by next step's leading barrier
    }
}

// ---------------- main: batched vector chain ----------------
__global__ void __launch_bounds__(256, 1) mps_chain(
    const float* __restrict__ x, const float* __restrict__ core0,
    const float* __restrict__ classifier, float* __restrict__ out)
{
    __shared__ char sm[SMEM_MAIN];
    uint32_t smb = smem_u32(sm);
    const int tid = threadIdx.x, lane = tid & 31, wc = tid >> 5;
    const int b0 = blockIdx.x * 16;

    float* XS   = (float*)(sm + XS_OFF);
    float* LOGS = (float*)(sm + LG_OFF);
    float* RINV = (float*)(sm + RI_OFF);
    float* LTOT = (float*)(sm + LT_OFF);

    #pragma unroll
    for (int it = 0; it < 16; ++it) {
        int idx = it * 256 + tid;
        XS[idx] = x[(size_t)(b0 + (idx >> 8)) * 256 + (idx & 255)];
    }
    if (tid < 16) LOGS[tid] = 0.f;
    __syncthreads();

    // init V0[bb][h]
    #pragma unroll
    for (int it = 0; it < 8; ++it) {
        int idx = it * 256 + tid;
        int bb = idx >> 7, h = idx & 127;
        float xv = XS[bb * 256];
        float v = (1.f - xv) * core0[h] + xv * core0[HD + h];
        *(__nv_bfloat16*)(sm + V0_OFF + bb * (PITCHV * 2) + h * 2) = __float2bfloat16(v);
    }
    // step 0's leading barrier covers visibility

    const int l15 = lane & 15, lhi = (lane >> 4) << 3;
    const int r = lane >> 2, q = lane & 3;
    const uint32_t fragbase = (uint32_t)(wc * 16) * 32 + lane;

    // preload B(0)
    uint4 B0[16], B1[16];
    {
        const uint4* bp = (const uint4*)g_perm + fragbase;
        #pragma unroll
        for (int i = 0; i < 16; ++i) B0[i] = bp[i * 32];
    }

    for (int mm = 0; mm < 127; ++mm) {
        chain_step(2 * mm,     true, B0, B1, sm, smb, fragbase, lane, wc, l15, lhi, r, q);
        chain_step(2 * mm + 1, true, B1, B0, sm, smb, fragbase, lane, wc, l15, lhi, r, q);
    }
    chain_step(254, false, B0, B1, sm, smb, fragbase, lane, wc, l15, lhi, r, q);
    __syncthreads();

    // final V lives in V1
    {
        int bb = tid >> 4, seg = tid & 15;
        const __nv_bfloat16* vrow = (const __nv_bfloat16*)(sm + V1_OFF + bb * (PITCHV * 2));
        float s = 0.f;
        #pragma unroll
        for (int j = 0; j < 8; ++j) {
            float f = __bfloat162float(vrow[seg * 8 + j]);
            s = fmaf(f, f, s);
        }
        #pragma unroll
        for (int o = 8; o > 0; o >>= 1) s += __shfl_xor_sync(0xffffffffu, s, o);
        if (seg == 0) {
            float nrm = fmaxf(sqrtf(s), 1e-30f);
            RINV[bb] = 1.f / nrm;
            LTOT[bb] = LOGS[bb] + logf(nrm);
        }
    }
    __syncthreads();

    if (tid < 16 * OUTC) {
        int bb = tid / OUTC, o = tid % OUTC;
        const __nv_bfloat16* vrow = (const __nv_bfloat16*)(sm + V1_OFF + bb * (PITCHV * 2));
        float s = 0.f;
        #pragma unroll
        for (int h = 0; h < HD; ++h)
            s = fmaf(__bfloat162float(vrow[h]), classifier[o * HD + h], s);
        out[(size_t)(b0 + bb) * OUTC + o] = s * RINV[bb] + LTOT[bb];
    }
}

extern "C" void kernel_launch(void* const* d_in, const int* in_sizes, int n_in,
                              void* d_out, int out_size)
{
    (void)in_sizes; (void)n_in; (void)out_size;
    const float* x          = (const float*)d_in[0];
    const float* core0      = (const float*)d_in[1];
    const float* cores      = (const float*)d_in[2];
    const float* classifier = (const float*)d_in[3];
    float*       out        = (float*)d_out;

    conv_perm<<<255, 256>>>(cores);
    mps_chain<<<4, 256>>>(x, core0, classifier, out);
}